// round 5
// baseline (speedup 1.0000x reference)
#include <cuda_runtime.h>
#include <cuda_bf16.h>

// Problem constants (fixed-shape problem)
#define NB 20000      // nodes
#define BB 64         // batch
#define EE 1280000    // edges

// ---------------- scratch (device globals; no runtime allocation) ----------------
__device__ float     g_xt[NB * BB];        // x transposed to [N, B]  (5.12 MB)
__device__ int       g_count[NB];          // histogram of dst; ZERO invariant at launch entry
__device__ int       g_rank[EE];           // per-edge rank within its dst bucket (5.12 MB)
__device__ int       g_row_start[NB + 1];  // CSR offsets
__device__ long long g_edge[EE];           // packed (coef<<32 | src), dst-sorted (10.24 MB)

__device__ __forceinline__ long long pack_edge(int s, float c) {
    return ((long long)__float_as_int(c) << 32) | (unsigned int)s;
}

// ---------------- K1: transpose x [B,N] -> xt [N,B]  +  rank-histogram of dst -----
// grid = (625, 2) x (32, 8) = 1250 blocks * 256 threads = 320000 = EE/4
__global__ __launch_bounds__(256) void k_pre(const float* __restrict__ x,
                                             const int* __restrict__ dst) {
    __shared__ float tile[32][33];
    const int bx = blockIdx.x, by = blockIdx.y;
    const int tx = threadIdx.x, ty = threadIdx.y;   // 32 x 8
    const int n0 = bx * 32, b0 = by * 32;

    // rank-histogram: rank[e] = atomicAdd(count[dst[e]], 1)  (overlaps the transpose)
    {
        int t = (by * gridDim.x + bx) * 256 + ty * 32 + tx;   // [0, EE/4)
        int4 d4 = reinterpret_cast<const int4*>(dst)[t];
        int4 r4;
        r4.x = atomicAdd(&g_count[d4.x], 1);
        r4.y = atomicAdd(&g_count[d4.y], 1);
        r4.z = atomicAdd(&g_count[d4.z], 1);
        r4.w = atomicAdd(&g_count[d4.w], 1);
        reinterpret_cast<int4*>(g_rank)[t] = r4;
    }

    #pragma unroll
    for (int i = 0; i < 32; i += 8) {
        int b = b0 + ty + i;
        int n = n0 + tx;                 // N = 625*32 exact, B = 2*32 exact
        tile[ty + i][tx] = x[b * NB + n];
    }
    __syncthreads();
    #pragma unroll
    for (int i = 0; i < 32; i += 8) {
        int n = n0 + ty + i;
        int b = b0 + tx;
        g_xt[n * BB + b] = tile[tx][ty + i];
    }
}

// ---------------- K2: single-block exclusive scan (20000 elements) ----------------
__global__ __launch_bounds__(1024) void k_scan() {
    __shared__ int warp_sums[32];
    const int t = threadIdx.x;
    const int lane = t & 31, wid = t >> 5;
    const int base = t * 20;             // 1024 * 20 = 20480 >= 20000

    int cnt[20];
    int sum = 0;
    #pragma unroll
    for (int k = 0; k < 20; k++) {
        int idx = base + k;
        cnt[k] = (idx < NB) ? g_count[idx] : 0;
        sum += cnt[k];
    }

    int v = sum;
    #pragma unroll
    for (int o = 1; o < 32; o <<= 1) {
        int u = __shfl_up_sync(0xFFFFFFFFu, v, o);
        if (lane >= o) v += u;
    }
    if (lane == 31) warp_sums[wid] = v;
    __syncthreads();
    if (wid == 0) {
        int w = warp_sums[lane];
        #pragma unroll
        for (int o = 1; o < 32; o <<= 1) {
            int u = __shfl_up_sync(0xFFFFFFFFu, w, o);
            if (lane >= o) w += u;
        }
        warp_sums[lane] = w;
    }
    __syncthreads();

    int warp_prefix = (wid > 0) ? warp_sums[wid - 1] : 0;
    int excl = warp_prefix + (v - sum);
    int run = excl;
    #pragma unroll
    for (int k = 0; k < 20; k++) {
        int idx = base + k;
        if (idx < NB) {
            g_row_start[idx] = run;
            run += cnt[k];
        }
    }
    if (t == 1023) g_row_start[NB] = run;   // = EE
}

// ---------------- K3: atomic-free scatter (8 edges/thread) ------------------------
// pos = row_start[dst] + rank.  Also re-zeroes g_count (restores launch invariant).
__global__ __launch_bounds__(256) void k_scatter(const int* __restrict__ src,
                                                 const int* __restrict__ dst,
                                                 const float* __restrict__ adj,
                                                 const float* __restrict__ w) {
    int t = blockIdx.x * 256 + threadIdx.x;          // 625 blocks -> EE/8 = 160000 threads

    const int4*   src4 = reinterpret_cast<const int4*>(src);
    const int4*   dst4 = reinterpret_cast<const int4*>(dst);
    const float4* adj4 = reinterpret_cast<const float4*>(adj);
    const float4* w4p  = reinterpret_cast<const float4*>(w);
    const int4*   rnk4 = reinterpret_cast<const int4*>(g_rank);

    int4   sA = src4[2 * t],  sB = src4[2 * t + 1];
    int4   dA = dst4[2 * t],  dB = dst4[2 * t + 1];
    float4 aA = adj4[2 * t],  aB = adj4[2 * t + 1];
    float4 wA = w4p[2 * t],   wB = w4p[2 * t + 1];
    int4   rA = rnk4[2 * t],  rB = rnk4[2 * t + 1];

    // restore zero invariant for next launch (count consumed by k_scan)
    if (t < NB) g_count[t] = 0;

    int p0 = g_row_start[dA.x] + rA.x;
    int p1 = g_row_start[dA.y] + rA.y;
    int p2 = g_row_start[dA.z] + rA.z;
    int p3 = g_row_start[dA.w] + rA.w;
    int p4 = g_row_start[dB.x] + rB.x;
    int p5 = g_row_start[dB.y] + rB.y;
    int p6 = g_row_start[dB.z] + rB.z;
    int p7 = g_row_start[dB.w] + rB.w;

    g_edge[p0] = pack_edge(sA.x, aA.x * wA.x);
    g_edge[p1] = pack_edge(sA.y, aA.y * wA.y);
    g_edge[p2] = pack_edge(sA.z, aA.z * wA.z);
    g_edge[p3] = pack_edge(sA.w, aA.w * wA.w);
    g_edge[p4] = pack_edge(sB.x, aB.x * wB.x);
    g_edge[p5] = pack_edge(sB.y, aB.y * wB.y);
    g_edge[p6] = pack_edge(sB.z, aB.z * wB.z);
    g_edge[p7] = pack_edge(sB.w, aB.w * wB.w);
}

// ---------------- K4: gather-SpMM + fused epilogue --------------------------------
// 8 nodes per block, 2 warps per node (edge list split in half).
// Half-warp per edge: 16 lanes x float4 = full 256B x-row; one warp does
// 2 edges per step (1 LDS.64 + 1 LDG.128 + 4 FFMA per step).
__global__ __launch_bounds__(512) void k_spmm(const float* __restrict__ x,      // for x[0, :]
                                              const float* __restrict__ self_w,
                                              const float* __restrict__ bias,
                                              float* __restrict__ out) {
    __shared__ long long s_pay[16][33];   // 32 payloads per warp (+pad)
    __shared__ float4    s_red[8][16];    // partial from odd warp
    __shared__ float     s_out[8][68];    // [node][batch] staged output (row 272B, 16B-aligned)

    const int warp = threadIdx.x >> 5;
    const int lane = threadIdx.x & 31;
    const int sub  = lane >> 4;           // which edge of the pair
    const int l16  = lane & 15;           // covers batch [4*l16, 4*l16+4)
    const int node = warp >> 1;           // 0..7
    const int half = warp & 1;
    const int n = blockIdx.x * 8 + node;  // NB = 2500 * 8 exact

    const int start = g_row_start[n];
    const int end   = g_row_start[n + 1];
    const int mid   = (start + end) >> 1;
    const int lo    = half ? mid : start;
    const int hi    = half ? end : mid;

    const float4* __restrict__ xt4 = reinterpret_cast<const float4*>(g_xt);

    float4 acc = make_float4(0.f, 0.f, 0.f, 0.f);

    for (int base = lo; base < hi; base += 32) {
        const int cnt = min(32, hi - base);
        // pad with zero payload (src=0, coef=0): harmless gather of row 0
        s_pay[warp][lane] = (lane < cnt) ? g_edge[base + lane] : 0ll;
        __syncwarp();

        const int nsteps = (cnt + 1) >> 1;   // 2 edges per step
        int k = 0;
        for (; k + 4 <= nsteps; k += 4) {
            #pragma unroll
            for (int u = 0; u < 4; u++) {
                long long p = s_pay[warp][2 * (k + u) + sub];
                unsigned int s = (unsigned int)p;            // low reg: src
                float c = __int_as_float((int)(p >> 32));    // high reg: coef
                float4 v = xt4[s * 16 + l16];
                acc.x = fmaf(c, v.x, acc.x);
                acc.y = fmaf(c, v.y, acc.y);
                acc.z = fmaf(c, v.z, acc.z);
                acc.w = fmaf(c, v.w, acc.w);
            }
        }
        for (; k < nsteps; k++) {
            long long p = s_pay[warp][2 * k + sub];
            unsigned int s = (unsigned int)p;
            float c = __int_as_float((int)(p >> 32));
            float4 v = xt4[s * 16 + l16];
            acc.x = fmaf(c, v.x, acc.x);
            acc.y = fmaf(c, v.y, acc.y);
            acc.z = fmaf(c, v.z, acc.z);
            acc.w = fmaf(c, v.w, acc.w);
        }
        __syncwarp();
    }

    // combine the two sub-half edge streams (lanes l and l^16 hold same batch range)
    acc.x += __shfl_xor_sync(0xFFFFFFFFu, acc.x, 16);
    acc.y += __shfl_xor_sync(0xFFFFFFFFu, acc.y, 16);
    acc.z += __shfl_xor_sync(0xFFFFFFFFu, acc.z, 16);
    acc.w += __shfl_xor_sync(0xFFFFFFFFu, acc.w, 16);

    if (half == 1 && sub == 0) s_red[node][l16] = acc;
    __syncthreads();

    if (half == 0 && sub == 0) {
        float4 r = s_red[node][l16];
        const float sl = x[n] * self_w[n];   // x[0*N + n]
        const float bv = bias[n];
        float4 o;
        o.x = fmaxf((acc.x + r.x) * sl + bv, 0.0f);
        o.y = fmaxf((acc.y + r.y) * sl + bv, 0.0f);
        o.z = fmaxf((acc.z + r.z) * sl + bv, 0.0f);
        o.w = fmaxf((acc.w + r.w) * sl + bv, 0.0f);
        *reinterpret_cast<float4*>(&s_out[node][4 * l16]) = o;
    }
    __syncthreads();

    // coalesced output: 512 threads = 8 nodes x 64 batch
    const int j = threadIdx.x & 7;        // node within block
    const int b = threadIdx.x >> 3;       // batch
    out[b * NB + blockIdx.x * 8 + j] = s_out[j][b];
}

// ---------------- launch -----------------------------------------------------------
extern "C" void kernel_launch(void* const* d_in, const int* in_sizes, int n_in,
                              void* d_out, int out_size) {
    const float* x      = (const float*)d_in[0];   // [B, N]
    const float* adj    = (const float*)d_in[1];   // [E]
    const float* w      = (const float*)d_in[2];   // [E]
    const float* self_w = (const float*)d_in[3];   // [N]
    const float* bias   = (const float*)d_in[4];   // [N]
    const int*   src    = (const int*)d_in[5];     // [E]
    const int*   dst    = (const int*)d_in[6];     // [E]
    float*       out    = (float*)d_out;           // [B, N]

    dim3 tgrid(NB / 32, BB / 32);                  // 625 x 2 = 1250 blocks
    dim3 tblk(32, 8);
    k_pre<<<tgrid, tblk>>>(x, dst);                // transpose + rank-histogram

    k_scan<<<1, 1024>>>();

    k_scatter<<<EE / 2048, 256>>>(src, dst, adj, w);  // atomic-free permute

    k_spmm<<<NB / 8, 512>>>(x, self_w, bias, out);
}

// round 6
// speedup vs baseline: 1.2178x; 1.2178x over previous
#include <cuda_runtime.h>
#include <cuda_bf16.h>

// Problem constants (fixed-shape problem)
#define NB 20000      // nodes
#define BB 64         // batch
#define EE 1280000    // edges

// ---------------- scratch (device globals; no runtime allocation) ----------------
__device__ float     g_xt[NB * BB];        // x transposed to [N, B]  (5.12 MB)
__device__ int       g_count[NB];          // histogram of dst; ZERO invariant at launch entry
__device__ int       g_rank[EE];           // per-edge rank within its dst bucket (5.12 MB)
__device__ int       g_row_start[NB + 1];  // CSR offsets
__device__ long long g_edge[EE];           // packed (coef<<32 | src*32), dst-sorted (10.24 MB)

__device__ __forceinline__ long long pack_edge(int s32, float c) {
    return ((long long)__float_as_int(c) << 32) | (unsigned int)s32;
}

// ---------------- K1: transpose x [B,N] -> xt [N,B]  +  rank-histogram of dst -----
// grid = (625, 2) x (32, 8) = 1250 blocks * 256 threads = 320000 = EE/4
__global__ __launch_bounds__(256) void k_pre(const float* __restrict__ x,
                                             const int* __restrict__ dst) {
    __shared__ float tile[32][33];
    const int bx = blockIdx.x, by = blockIdx.y;
    const int tx = threadIdx.x, ty = threadIdx.y;   // 32 x 8
    const int n0 = bx * 32, b0 = by * 32;

    // rank-histogram: rank[e] = atomicAdd(count[dst[e]], 1)  (overlaps the transpose)
    {
        int t = (by * gridDim.x + bx) * 256 + ty * 32 + tx;   // [0, EE/4)
        int4 d4 = reinterpret_cast<const int4*>(dst)[t];
        int4 r4;
        r4.x = atomicAdd(&g_count[d4.x], 1);
        r4.y = atomicAdd(&g_count[d4.y], 1);
        r4.z = atomicAdd(&g_count[d4.z], 1);
        r4.w = atomicAdd(&g_count[d4.w], 1);
        reinterpret_cast<int4*>(g_rank)[t] = r4;
    }

    #pragma unroll
    for (int i = 0; i < 32; i += 8) {
        int b = b0 + ty + i;
        int n = n0 + tx;                 // N = 625*32 exact, B = 2*32 exact
        tile[ty + i][tx] = x[b * NB + n];
    }
    __syncthreads();
    #pragma unroll
    for (int i = 0; i < 32; i += 8) {
        int n = n0 + ty + i;
        int b = b0 + tx;
        g_xt[n * BB + b] = tile[tx][ty + i];
    }
}

// ---------------- K2: single-block exclusive scan (20000 elements) ----------------
__global__ __launch_bounds__(1024) void k_scan() {
    __shared__ int warp_sums[32];
    const int t = threadIdx.x;
    const int lane = t & 31, wid = t >> 5;
    const int base = t * 20;             // 1024 * 20 = 20480 >= 20000

    int cnt[20];
    int sum = 0;
    #pragma unroll
    for (int k = 0; k < 20; k++) {
        int idx = base + k;
        cnt[k] = (idx < NB) ? g_count[idx] : 0;
        sum += cnt[k];
    }

    int v = sum;
    #pragma unroll
    for (int o = 1; o < 32; o <<= 1) {
        int u = __shfl_up_sync(0xFFFFFFFFu, v, o);
        if (lane >= o) v += u;
    }
    if (lane == 31) warp_sums[wid] = v;
    __syncthreads();
    if (wid == 0) {
        int w = warp_sums[lane];
        #pragma unroll
        for (int o = 1; o < 32; o <<= 1) {
            int u = __shfl_up_sync(0xFFFFFFFFu, w, o);
            if (lane >= o) w += u;
        }
        warp_sums[lane] = w;
    }
    __syncthreads();

    int warp_prefix = (wid > 0) ? warp_sums[wid - 1] : 0;
    int excl = warp_prefix + (v - sum);
    int run = excl;
    #pragma unroll
    for (int k = 0; k < 20; k++) {
        int idx = base + k;
        if (idx < NB) {
            g_row_start[idx] = run;
            run += cnt[k];
        }
    }
    if (t == 1023) g_row_start[NB] = run;   // = EE
}

// ---------------- K3: atomic-free scatter (8 edges/thread) ------------------------
// pos = row_start[dst] + rank.  Stores src pre-scaled by 32 (float2-row index).
// Also re-zeroes g_count (restores launch invariant).
__global__ __launch_bounds__(256) void k_scatter(const int* __restrict__ src,
                                                 const int* __restrict__ dst,
                                                 const float* __restrict__ adj,
                                                 const float* __restrict__ w) {
    int t = blockIdx.x * 256 + threadIdx.x;          // 625 blocks -> EE/8 = 160000 threads

    const int4*   src4 = reinterpret_cast<const int4*>(src);
    const int4*   dst4 = reinterpret_cast<const int4*>(dst);
    const float4* adj4 = reinterpret_cast<const float4*>(adj);
    const float4* w4p  = reinterpret_cast<const float4*>(w);
    const int4*   rnk4 = reinterpret_cast<const int4*>(g_rank);

    int4   sA = src4[2 * t],  sB = src4[2 * t + 1];
    int4   dA = dst4[2 * t],  dB = dst4[2 * t + 1];
    float4 aA = adj4[2 * t],  aB = adj4[2 * t + 1];
    float4 wA = w4p[2 * t],   wB = w4p[2 * t + 1];
    int4   rA = rnk4[2 * t],  rB = rnk4[2 * t + 1];

    // restore zero invariant for next launch (count consumed by k_scan)
    if (t < NB) g_count[t] = 0;

    int p0 = g_row_start[dA.x] + rA.x;
    int p1 = g_row_start[dA.y] + rA.y;
    int p2 = g_row_start[dA.z] + rA.z;
    int p3 = g_row_start[dA.w] + rA.w;
    int p4 = g_row_start[dB.x] + rB.x;
    int p5 = g_row_start[dB.y] + rB.y;
    int p6 = g_row_start[dB.z] + rB.z;
    int p7 = g_row_start[dB.w] + rB.w;

    g_edge[p0] = pack_edge(sA.x * 32, aA.x * wA.x);
    g_edge[p1] = pack_edge(sA.y * 32, aA.y * wA.y);
    g_edge[p2] = pack_edge(sA.z * 32, aA.z * wA.z);
    g_edge[p3] = pack_edge(sA.w * 32, aA.w * wA.w);
    g_edge[p4] = pack_edge(sB.x * 32, aB.x * wB.x);
    g_edge[p5] = pack_edge(sB.y * 32, aB.y * wB.y);
    g_edge[p6] = pack_edge(sB.z * 32, aB.z * wB.z);
    g_edge[p7] = pack_edge(sB.w * 32, aB.w * wB.w);
}

// ---------------- K4: gather-SpMM + fused epilogue --------------------------------
// 8 nodes per block, 2 warps per node (edge list split in half).
// Lane holds float2 accumulators (b = 2*lane, 2*lane+1), 2 chains (even/odd edge).
// Payloads staged in smem; consumed as LDS.128 pairs (row stride 272B, 16B-aligned).
__global__ __launch_bounds__(512) void k_spmm(const float* __restrict__ x,      // for x[0, :]
                                              const float* __restrict__ self_w,
                                              const float* __restrict__ bias,
                                              float* __restrict__ out) {
    __shared__ long long s_pay[16][34];   // 32 payloads per warp; row = 272B (17x16B)
    __shared__ float2    s_red[8][32];    // partial from odd warp
    __shared__ float     s_out[8][65];    // [node][batch] staged output

    const int warp = threadIdx.x >> 5;
    const int lane = threadIdx.x & 31;
    const int node = warp >> 1;           // 0..7
    const int half = warp & 1;
    const int n = blockIdx.x * 8 + node;  // NB = 2500 * 8 exact

    const int start = g_row_start[n];
    const int end   = g_row_start[n + 1];
    const int mid   = (start + end) >> 1;
    const int lo    = half ? mid : start;
    const int hi    = half ? end : mid;

    const float2* __restrict__ xt2 = reinterpret_cast<const float2*>(g_xt);

    float2 acc0 = make_float2(0.f, 0.f);
    float2 acc1 = make_float2(0.f, 0.f);

    for (int base = lo; base < hi; base += 32) {
        const int cnt = min(32, hi - base);
        if (lane < cnt) s_pay[warp][lane] = g_edge[base + lane];
        __syncwarp();

        const int npair = cnt >> 1;
        int k = 0;
        for (; k + 4 <= npair; k += 4) {           // 8 edges per iter
            #pragma unroll
            for (int u = 0; u < 4; u++) {
                longlong2 pp = *reinterpret_cast<const longlong2*>(&s_pay[warp][2 * (k + u)]);
                unsigned int s0 = (unsigned int)pp.x;            // pre-scaled src*32
                float        c0 = __int_as_float((int)(pp.x >> 32));
                unsigned int s1 = (unsigned int)pp.y;
                float        c1 = __int_as_float((int)(pp.y >> 32));
                float2 v0 = xt2[s0 + lane];
                float2 v1 = xt2[s1 + lane];
                acc0.x = fmaf(c0, v0.x, acc0.x);
                acc0.y = fmaf(c0, v0.y, acc0.y);
                acc1.x = fmaf(c1, v1.x, acc1.x);
                acc1.y = fmaf(c1, v1.y, acc1.y);
            }
        }
        for (; k < npair; k++) {
            longlong2 pp = *reinterpret_cast<const longlong2*>(&s_pay[warp][2 * k]);
            unsigned int s0 = (unsigned int)pp.x;
            float        c0 = __int_as_float((int)(pp.x >> 32));
            unsigned int s1 = (unsigned int)pp.y;
            float        c1 = __int_as_float((int)(pp.y >> 32));
            float2 v0 = xt2[s0 + lane];
            float2 v1 = xt2[s1 + lane];
            acc0.x = fmaf(c0, v0.x, acc0.x);
            acc0.y = fmaf(c0, v0.y, acc0.y);
            acc1.x = fmaf(c1, v1.x, acc1.x);
            acc1.y = fmaf(c1, v1.y, acc1.y);
        }
        if (cnt & 1) {                              // odd tail edge
            long long p = s_pay[warp][cnt - 1];
            unsigned int s = (unsigned int)p;
            float        c = __int_as_float((int)(p >> 32));
            float2 v = xt2[s + lane];
            acc0.x = fmaf(c, v.x, acc0.x);
            acc0.y = fmaf(c, v.y, acc0.y);
        }
        __syncwarp();
    }

    float ax = acc0.x + acc1.x;
    float ay = acc0.y + acc1.y;

    if (half == 1) s_red[node][lane] = make_float2(ax, ay);
    __syncthreads();

    if (half == 0) {
        float2 r = s_red[node][lane];
        ax += r.x;  ay += r.y;
        const float sl = x[n] * self_w[n];   // x[0*N + n]
        const float bv = bias[n];
        s_out[node][2 * lane]     = fmaxf(ax * sl + bv, 0.0f);
        s_out[node][2 * lane + 1] = fmaxf(ay * sl + bv, 0.0f);
    }
    __syncthreads();

    // coalesced output: 512 threads = 8 nodes x 64 batch
    const int j = threadIdx.x & 7;        // node within block
    const int b = threadIdx.x >> 3;       // batch
    out[b * NB + blockIdx.x * 8 + j] = s_out[j][b];
}

// ---------------- launch -----------------------------------------------------------
extern "C" void kernel_launch(void* const* d_in, const int* in_sizes, int n_in,
                              void* d_out, int out_size) {
    const float* x      = (const float*)d_in[0];   // [B, N]
    const float* adj    = (const float*)d_in[1];   // [E]
    const float* w      = (const float*)d_in[2];   // [E]
    const float* self_w = (const float*)d_in[3];   // [N]
    const float* bias   = (const float*)d_in[4];   // [N]
    const int*   src    = (const int*)d_in[5];     // [E]
    const int*   dst    = (const int*)d_in[6];     // [E]
    float*       out    = (float*)d_out;           // [B, N]

    dim3 tgrid(NB / 32, BB / 32);                  // 625 x 2 = 1250 blocks
    dim3 tblk(32, 8);
    k_pre<<<tgrid, tblk>>>(x, dst);                // transpose + rank-histogram

    k_scan<<<1, 1024>>>();

    k_scatter<<<EE / 2048, 256>>>(src, dst, adj, w);  // atomic-free permute

    k_spmm<<<NB / 8, 512>>>(x, self_w, bias, out);
}

// round 7
// speedup vs baseline: 1.5137x; 1.2429x over previous
#include <cuda_runtime.h>
#include <cuda_fp16.h>
#include <cuda_bf16.h>

// Problem constants (fixed-shape problem)
#define NB 20000      // nodes
#define BB 64         // batch
#define EE 1280000    // edges

// ---------------- scratch (device globals; no runtime allocation) ----------------
__device__ __half    g_xth[NB * BB];       // x transposed to [N, B] in fp16 (2.56 MB)
__device__ int       g_count[NB];          // histogram of dst; ZERO invariant at launch entry
__device__ int       g_rank[EE];           // per-edge rank within its dst bucket (5.12 MB)
__device__ int       g_row_start[NB + 1];  // CSR offsets
__device__ long long g_edge[EE];           // packed (coef<<32 | src), dst-sorted (10.24 MB)

__device__ __forceinline__ long long pack_edge(int s, float c) {
    return ((long long)__float_as_int(c) << 32) | (unsigned int)s;
}

// ---------------- K1: transpose x [B,N] -> xth [N,B] (fp16) + rank-histogram ------
// grid = (625, 2) x (32, 8) = 1250 blocks * 256 threads = 320000 = EE/4
__global__ __launch_bounds__(256) void k_pre(const float* __restrict__ x,
                                             const int* __restrict__ dst) {
    __shared__ float tile[32][33];
    const int bx = blockIdx.x, by = blockIdx.y;
    const int tx = threadIdx.x, ty = threadIdx.y;   // 32 x 8
    const int n0 = bx * 32, b0 = by * 32;
    const int t  = ty * 32 + tx;                    // 0..255

    // rank-histogram: rank[e] = atomicAdd(count[dst[e]], 1)  (overlaps the transpose)
    {
        int e4 = (by * gridDim.x + bx) * 256 + t;   // [0, EE/4)
        int4 d4 = reinterpret_cast<const int4*>(dst)[e4];
        int4 r4;
        r4.x = atomicAdd(&g_count[d4.x], 1);
        r4.y = atomicAdd(&g_count[d4.y], 1);
        r4.z = atomicAdd(&g_count[d4.z], 1);
        r4.w = atomicAdd(&g_count[d4.w], 1);
        reinterpret_cast<int4*>(g_rank)[e4] = r4;
    }

    // tile[b_local][n_local] = x[b, n]
    #pragma unroll
    for (int i = 0; i < 32; i += 8) {
        int b = b0 + ty + i;
        int n = n0 + tx;                 // N = 625*32 exact, B = 2*32 exact
        tile[ty + i][tx] = x[b * NB + n];
    }
    __syncthreads();

    // write half2: 32 n-rows x 16 b-pairs = 512 items, 256 threads x 2
    __half2* __restrict__ xth2 = reinterpret_cast<__half2*>(g_xth);
    #pragma unroll
    for (int i = 0; i < 2; i++) {
        int idx = i * 256 + t;
        int nl = idx >> 4;               // 0..31
        int bp = idx & 15;               // half2 pair index
        float v0 = tile[2 * bp][nl];
        float v1 = tile[2 * bp + 1][nl];
        xth2[(n0 + nl) * 32 + (b0 >> 1) + bp] = __floats2half2_rn(v0, v1);
    }
}

// ---------------- K2: single-block exclusive scan (20000 elements) ----------------
__global__ __launch_bounds__(1024) void k_scan() {
    __shared__ int warp_sums[32];
    const int t = threadIdx.x;
    const int lane = t & 31, wid = t >> 5;
    const int base = t * 20;             // 1024 * 20 = 20480 >= 20000

    int cnt[20];
    int sum = 0;
    #pragma unroll
    for (int k = 0; k < 20; k++) {
        int idx = base + k;
        cnt[k] = (idx < NB) ? g_count[idx] : 0;
        sum += cnt[k];
    }

    int v = sum;
    #pragma unroll
    for (int o = 1; o < 32; o <<= 1) {
        int u = __shfl_up_sync(0xFFFFFFFFu, v, o);
        if (lane >= o) v += u;
    }
    if (lane == 31) warp_sums[wid] = v;
    __syncthreads();
    if (wid == 0) {
        int w = warp_sums[lane];
        #pragma unroll
        for (int o = 1; o < 32; o <<= 1) {
            int u = __shfl_up_sync(0xFFFFFFFFu, w, o);
            if (lane >= o) w += u;
        }
        warp_sums[lane] = w;
    }
    __syncthreads();

    int warp_prefix = (wid > 0) ? warp_sums[wid - 1] : 0;
    int excl = warp_prefix + (v - sum);
    int run = excl;
    #pragma unroll
    for (int k = 0; k < 20; k++) {
        int idx = base + k;
        if (idx < NB) {
            g_row_start[idx] = run;
            run += cnt[k];
        }
    }
    if (t == 1023) g_row_start[NB] = run;   // = EE
}

// ---------------- K3: atomic-free scatter (8 edges/thread) ------------------------
// pos = row_start[dst] + rank.  Also re-zeroes g_count (restores launch invariant).
__global__ __launch_bounds__(256) void k_scatter(const int* __restrict__ src,
                                                 const int* __restrict__ dst,
                                                 const float* __restrict__ adj,
                                                 const float* __restrict__ w) {
    int t = blockIdx.x * 256 + threadIdx.x;          // 625 blocks -> EE/8 = 160000 threads

    const int4*   src4 = reinterpret_cast<const int4*>(src);
    const int4*   dst4 = reinterpret_cast<const int4*>(dst);
    const float4* adj4 = reinterpret_cast<const float4*>(adj);
    const float4* w4p  = reinterpret_cast<const float4*>(w);
    const int4*   rnk4 = reinterpret_cast<const int4*>(g_rank);

    int4   sA = src4[2 * t],  sB = src4[2 * t + 1];
    int4   dA = dst4[2 * t],  dB = dst4[2 * t + 1];
    float4 aA = adj4[2 * t],  aB = adj4[2 * t + 1];
    float4 wA = w4p[2 * t],   wB = w4p[2 * t + 1];
    int4   rA = rnk4[2 * t],  rB = rnk4[2 * t + 1];

    // restore zero invariant for next launch (count consumed by k_scan)
    if (t < NB) g_count[t] = 0;

    int p0 = g_row_start[dA.x] + rA.x;
    int p1 = g_row_start[dA.y] + rA.y;
    int p2 = g_row_start[dA.z] + rA.z;
    int p3 = g_row_start[dA.w] + rA.w;
    int p4 = g_row_start[dB.x] + rB.x;
    int p5 = g_row_start[dB.y] + rB.y;
    int p6 = g_row_start[dB.z] + rB.z;
    int p7 = g_row_start[dB.w] + rB.w;

    g_edge[p0] = pack_edge(sA.x, aA.x * wA.x);
    g_edge[p1] = pack_edge(sA.y, aA.y * wA.y);
    g_edge[p2] = pack_edge(sA.z, aA.z * wA.z);
    g_edge[p3] = pack_edge(sA.w, aA.w * wA.w);
    g_edge[p4] = pack_edge(sB.x, aB.x * wB.x);
    g_edge[p5] = pack_edge(sB.y, aB.y * wB.y);
    g_edge[p6] = pack_edge(sB.z, aB.z * wB.z);
    g_edge[p7] = pack_edge(sB.w, aB.w * wB.w);
}

// ---------------- K4: gather-SpMM + fused epilogue --------------------------------
// Exact R3 structure (best measured: 34.8us) with half2 x-rows instead of float2.
// 8 nodes per block, 2 warps per node; lane accumulates fp32 for b=2*lane, 2*lane+1.
__global__ __launch_bounds__(512) void k_spmm(const float* __restrict__ x,      // for x[0, :]
                                              const float* __restrict__ self_w,
                                              const float* __restrict__ bias,
                                              float* __restrict__ out) {
    __shared__ long long s_pay[16][33];   // 32 payloads per warp (+pad)
    __shared__ float2    s_red[8][32];    // partial from odd warp
    __shared__ float     s_out[8][65];    // [node][batch] staged output

    const int warp = threadIdx.x >> 5;
    const int lane = threadIdx.x & 31;
    const int node = warp >> 1;           // 0..7
    const int half = warp & 1;
    const int n = blockIdx.x * 8 + node;  // NB = 2500 * 8 exact

    const int start = g_row_start[n];
    const int end   = g_row_start[n + 1];
    const int mid   = (start + end) >> 1;
    const int lo    = half ? mid : start;
    const int hi    = half ? end : mid;

    const __half2* __restrict__ xth2 = reinterpret_cast<const __half2*>(g_xth);

    float ax = 0.f, ay = 0.f;

    for (int base = lo; base < hi; base += 32) {
        const int cnt = min(32, hi - base);
        if (lane < cnt) s_pay[warp][lane] = g_edge[base + lane];
        __syncwarp();

        int k = 0;
        for (; k + 8 <= cnt; k += 8) {
            long long p[8];
            #pragma unroll
            for (int u = 0; u < 8; u++) p[u] = s_pay[warp][k + u];
            #pragma unroll
            for (int u = 0; u < 8; u++) {
                unsigned int s = (unsigned int)p[u];
                float c = __int_as_float((int)(p[u] >> 32));
                float2 v = __half22float2(xth2[s * 32 + lane]);
                ax = fmaf(c, v.x, ax);
                ay = fmaf(c, v.y, ay);
            }
        }
        for (; k < cnt; k++) {
            long long p = s_pay[warp][k];
            unsigned int s = (unsigned int)p;
            float c = __int_as_float((int)(p >> 32));
            float2 v = __half22float2(xth2[s * 32 + lane]);
            ax = fmaf(c, v.x, ax);
            ay = fmaf(c, v.y, ay);
        }
        __syncwarp();
    }

    if (half == 1) s_red[node][lane] = make_float2(ax, ay);
    __syncthreads();

    if (half == 0) {
        float2 r = s_red[node][lane];
        ax += r.x;  ay += r.y;
        const float sl = x[n] * self_w[n];   // x[0*N + n]  (fp32, exact)
        const float bv = bias[n];
        s_out[node][2 * lane]     = fmaxf(ax * sl + bv, 0.0f);
        s_out[node][2 * lane + 1] = fmaxf(ay * sl + bv, 0.0f);
    }
    __syncthreads();

    // coalesced output: 512 threads = 8 nodes x 64 batch
    const int j = threadIdx.x & 7;        // node within block
    const int b = threadIdx.x >> 3;       // batch
    out[b * NB + blockIdx.x * 8 + j] = s_out[j][b];
}

// ---------------- launch -----------------------------------------------------------
extern "C" void kernel_launch(void* const* d_in, const int* in_sizes, int n_in,
                              void* d_out, int out_size) {
    const float* x      = (const float*)d_in[0];   // [B, N]
    const float* adj    = (const float*)d_in[1];   // [E]
    const float* w      = (const float*)d_in[2];   // [E]
    const float* self_w = (const float*)d_in[3];   // [N]
    const float* bias   = (const float*)d_in[4];   // [N]
    const int*   src    = (const int*)d_in[5];     // [E]
    const int*   dst    = (const int*)d_in[6];     // [E]
    float*       out    = (float*)d_out;           // [B, N]

    dim3 tgrid(NB / 32, BB / 32);                  // 625 x 2 = 1250 blocks
    dim3 tblk(32, 8);
    k_pre<<<tgrid, tblk>>>(x, dst);                // transpose(fp16) + rank-histogram

    k_scan<<<1, 1024>>>();

    k_scatter<<<EE / 2048, 256>>>(src, dst, adj, w);  // atomic-free permute

    k_spmm<<<NB / 8, 512>>>(x, self_w, bias, out);
}